// round 1
// baseline (speedup 1.0000x reference)
#include <cuda_runtime.h>
#include <cuda_bf16.h>
#include <cstddef>

// Problem constants
#define NPART 128
#define NDIM  128
#define BATCH 4096

// softmax probabilities staging (scratch: __device__ global, no allocs)
__device__ float g_psoft[NPART];

// ---------------------------------------------------------------------------
// Kernel 1: softmax over logp[128] -> g_psoft
// ---------------------------------------------------------------------------
__global__ void softmax_k(const float* __restrict__ logp) {
    __shared__ float sh[NPART];
    int t = threadIdx.x;
    float v = logp[t];

    // max reduce
    sh[t] = v;
    __syncthreads();
    #pragma unroll
    for (int s = 64; s > 0; s >>= 1) {
        if (t < s) sh[t] = fmaxf(sh[t], sh[t + s]);
        __syncthreads();
    }
    float m = sh[0];
    __syncthreads();

    float e = __expf(v - m);
    sh[t] = e;
    __syncthreads();
    #pragma unroll
    for (int s = 64; s > 0; s >>= 1) {
        if (t < s) sh[t] = sh[t] + sh[t + s];
        __syncthreads();
    }
    float denom = sh[0];
    g_psoft[t] = e / denom;
}

// ---------------------------------------------------------------------------
// Kernel 2: main matvec. One block per sample, 128 threads.
// out[b*128 + i] = pos[r,i] + dot(sigma[r,i,:], y[b,:])
// ---------------------------------------------------------------------------
__global__ __launch_bounds__(NDIM) void matvec_k(
    const float* __restrict__ gaussian,
    const float* __restrict__ pos,
    const float* __restrict__ sigma,
    const int*   __restrict__ randind,
    float*       __restrict__ out)
{
    int b = blockIdx.x;
    int i = threadIdx.x;

    __shared__ float y[NDIM];
    y[i] = gaussian[(size_t)b * NDIM + i];
    __syncthreads();

    int r = randind[b];

    const float4* __restrict__ srow =
        (const float4*)(sigma + ((size_t)r * NDIM + i) * NDIM);
    const float4* y4 = (const float4*)y;

    float acc = 0.0f;
    #pragma unroll
    for (int j = 0; j < NDIM / 4; j++) {
        float4 s  = __ldg(&srow[j]);
        float4 yy = y4[j];
        acc = fmaf(s.x, yy.x, acc);
        acc = fmaf(s.y, yy.y, acc);
        acc = fmaf(s.z, yy.z, acc);
        acc = fmaf(s.w, yy.w, acc);
    }

    out[(size_t)b * NDIM + i] = pos[(size_t)r * NDIM + i] + acc;
}

// ---------------------------------------------------------------------------
// Kernel 3: aux outputs — weights (softmax gather) and randind-as-float.
// ---------------------------------------------------------------------------
__global__ void aux_k(const int* __restrict__ randind,
                      float* __restrict__ wout,
                      float* __restrict__ rout)
{
    int b = blockIdx.x * blockDim.x + threadIdx.x;
    if (b < BATCH) {
        int r = randind[b];
        if (wout) wout[b] = g_psoft[r];
        if (rout) rout[b] = (float)r;
    }
}

// ---------------------------------------------------------------------------
// Launch
// ---------------------------------------------------------------------------
extern "C" void kernel_launch(void* const* d_in, const int* in_sizes, int n_in,
                              void* d_out, int out_size)
{
    // Defensive input matching by element count (all counts distinct):
    // gaussian 4096*128 = 524288, logp 128, pos 128*128 = 16384,
    // sigma 128*128*128 = 2097152, randind 4096.
    const float* gaussian = nullptr;
    const float* logp     = nullptr;
    const float* pos      = nullptr;
    const float* sigma    = nullptr;
    const int*   randind  = nullptr;

    for (int k = 0; k < n_in; k++) {
        switch (in_sizes[k]) {
            case BATCH * NDIM:       gaussian = (const float*)d_in[k]; break;
            case NPART:              logp     = (const float*)d_in[k]; break;
            case NPART * NDIM:       pos      = (const float*)d_in[k]; break;
            case NPART * NDIM * NDIM: sigma   = (const float*)d_in[k]; break;
            case BATCH:              randind  = (const int*)d_in[k];   break;
            default: break;
        }
    }

    float* out = (float*)d_out;

    softmax_k<<<1, NPART>>>(logp);
    matvec_k<<<BATCH, NDIM>>>(gaussian, pos, sigma, randind, out);

    // Optional tail outputs depending on harness flattening:
    // [out (524288)] [weights (4096)] [randind (4096)]
    float* wout = nullptr;
    float* rout = nullptr;
    const int OUT_MAIN = BATCH * NDIM;
    if (out_size >= OUT_MAIN + BATCH)     wout = out + OUT_MAIN;
    if (out_size >= OUT_MAIN + 2 * BATCH) rout = out + OUT_MAIN + BATCH;
    if (wout || rout) {
        aux_k<<<(BATCH + 255) / 256, 256>>>(randind, wout, rout);
    }
}

// round 2
// speedup vs baseline: 2.3566x; 2.3566x over previous
#include <cuda_runtime.h>
#include <cuda_bf16.h>
#include <cstddef>

#define NPART 128
#define NDIM  128
#define BATCH 4096
#define TILE_B 16

// ---------------- scratch (no allocs allowed) ----------------
__device__ float g_psoft[NPART];
__device__ int   g_count[NPART];
__device__ int   g_list[NPART][BATCH];   // worst-case capacity, 2 MB

// ---------------------------------------------------------------------------
// Kernel 1: softmax over logp[128] -> g_psoft ; also zero g_count.
// ---------------------------------------------------------------------------
__global__ void softmax_k(const float* __restrict__ logp) {
    __shared__ float sh[NPART];
    int t = threadIdx.x;
    g_count[t] = 0;

    float v = logp[t];
    sh[t] = v;
    __syncthreads();
    #pragma unroll
    for (int s = 64; s > 0; s >>= 1) {
        if (t < s) sh[t] = fmaxf(sh[t], sh[t + s]);
        __syncthreads();
    }
    float m = sh[0];
    __syncthreads();
    float e = __expf(v - m);
    sh[t] = e;
    __syncthreads();
    #pragma unroll
    for (int s = 64; s > 0; s >>= 1) {
        if (t < s) sh[t] = sh[t] + sh[t + s];
        __syncthreads();
    }
    g_psoft[t] = e / sh[0];
}

// ---------------------------------------------------------------------------
// Kernel 2: group samples by particle + emit aux tail outputs.
// ---------------------------------------------------------------------------
__global__ void group_k(const int* __restrict__ randind,
                        float* __restrict__ wout,
                        float* __restrict__ rout)
{
    int b = blockIdx.x * blockDim.x + threadIdx.x;
    if (b < BATCH) {
        int r = randind[b];
        int slot = atomicAdd(&g_count[r], 1);
        g_list[r][slot] = b;
        if (wout) wout[b] = g_psoft[r];
        if (rout) rout[b] = (float)r;
    }
}

// ---------------------------------------------------------------------------
// Kernel 3: per-particle batched GEMM. One CTA per particle, 256 threads.
// out[b][i] = pos[p][i] + sum_j sigma[p][i][j] * gaussian[b][j]
// smem: sig_t[j][i] (transposed, 64KB) + y tile [TILE_B][128] (8KB)
// ---------------------------------------------------------------------------
__global__ __launch_bounds__(256) void gemm_k(
    const float* __restrict__ gaussian,
    const float* __restrict__ pos,
    const float* __restrict__ sigma,
    float*       __restrict__ out)
{
    extern __shared__ float smem[];
    float* sig_t = smem;                 // [128][128] : sig_t[j*128 + i]
    float* ysh   = smem + NDIM * NDIM;   // [TILE_B][128]

    const int p   = blockIdx.x;
    const int tid = threadIdx.x;
    const int count = g_count[p];

    // ---- stage sigma[p] transposed ----
    // thread owns row i = tid%128 and j-half = (tid/128)*64.
    // gmem: lane-strided (512B apart) but each line fully consumed via L1.
    // smem writes: lanes on consecutive i -> conflict-free.
    {
        const int i  = tid & 127;
        const int jh = (tid >> 7) * 64;
        const float4* srow = (const float4*)(sigma + ((size_t)p * NDIM + i) * NDIM + jh);
        #pragma unroll
        for (int jj = 0; jj < 16; jj++) {
            float4 v = __ldg(&srow[jj]);
            int j = jh + jj * 4;
            sig_t[(j + 0) * NDIM + i] = v.x;
            sig_t[(j + 1) * NDIM + i] = v.y;
            sig_t[(j + 2) * NDIM + i] = v.z;
            sig_t[(j + 3) * NDIM + i] = v.w;
        }
    }

    if (count == 0) return;   // uniform per CTA; no divergence hazard

    const int tx = tid & 31;       // 32 i-groups
    const int ty = tid >> 5;       // 8 b-groups
    const int i0 = tx * 4;

    // pos row (L1-cached reuse across tiles)
    const float4 pv = __ldg((const float4*)(pos + (size_t)p * NDIM + i0));

    const int ntiles = (count + TILE_B - 1) / TILE_B;
    const int* __restrict__ list = g_list[p];

    for (int t = 0; t < ntiles; t++) {
        const int base = t * TILE_B;
        // ---- stage y tile (zero-fill past count) ----
        __syncthreads();   // protect previous tile's ysh reads
        for (int idx = tid; idx < TILE_B * NDIM; idx += 256) {
            int bl = idx >> 7;        // 0..15
            int j  = idx & 127;
            int gi = base + bl;
            ysh[idx] = (gi < count) ? __ldg(&gaussian[(size_t)list[gi] * NDIM + j]) : 0.0f;
        }
        __syncthreads();

        // ---- microkernel: 4 i x 2 b per thread ----
        float a0x = 0.f, a0y = 0.f, a0z = 0.f, a0w = 0.f;
        float a1x = 0.f, a1y = 0.f, a1z = 0.f, a1w = 0.f;
        const float* y0 = ysh + (ty * 2 + 0) * NDIM;
        const float* y1 = ysh + (ty * 2 + 1) * NDIM;

        #pragma unroll 8
        for (int j = 0; j < NDIM; j++) {
            float4 s = *(const float4*)(sig_t + j * NDIM + i0);
            float ya = y0[j];
            float yb = y1[j];
            a0x = fmaf(s.x, ya, a0x); a0y = fmaf(s.y, ya, a0y);
            a0z = fmaf(s.z, ya, a0z); a0w = fmaf(s.w, ya, a0w);
            a1x = fmaf(s.x, yb, a1x); a1y = fmaf(s.y, yb, a1y);
            a1z = fmaf(s.z, yb, a1z); a1w = fmaf(s.w, yb, a1w);
        }

        // ---- epilogue ----
        int gi0 = base + ty * 2 + 0;
        int gi1 = base + ty * 2 + 1;
        if (gi0 < count) {
            int b = list[gi0];
            float4 o; o.x = pv.x + a0x; o.y = pv.y + a0y; o.z = pv.z + a0z; o.w = pv.w + a0w;
            *(float4*)(out + (size_t)b * NDIM + i0) = o;
        }
        if (gi1 < count) {
            int b = list[gi1];
            float4 o; o.x = pv.x + a1x; o.y = pv.y + a1y; o.z = pv.z + a1z; o.w = pv.w + a1w;
            *(float4*)(out + (size_t)b * NDIM + i0) = o;
        }
    }
}

// ---------------------------------------------------------------------------
// Launch
// ---------------------------------------------------------------------------
extern "C" void kernel_launch(void* const* d_in, const int* in_sizes, int n_in,
                              void* d_out, int out_size)
{
    const float* gaussian = nullptr;
    const float* logp     = nullptr;
    const float* pos      = nullptr;
    const float* sigma    = nullptr;
    const int*   randind  = nullptr;

    for (int k = 0; k < n_in; k++) {
        switch (in_sizes[k]) {
            case BATCH * NDIM:        gaussian = (const float*)d_in[k]; break;
            case NPART:               logp     = (const float*)d_in[k]; break;
            case NPART * NDIM:        pos      = (const float*)d_in[k]; break;
            case NPART * NDIM * NDIM: sigma    = (const float*)d_in[k]; break;
            case BATCH:               randind  = (const int*)d_in[k];   break;
            default: break;
        }
    }

    float* out = (float*)d_out;
    float* wout = nullptr;
    float* rout = nullptr;
    const int OUT_MAIN = BATCH * NDIM;
    if (out_size >= OUT_MAIN + BATCH)     wout = out + OUT_MAIN;
    if (out_size >= OUT_MAIN + 2 * BATCH) rout = out + OUT_MAIN + BATCH;

    const int smem_bytes = (NDIM * NDIM + TILE_B * NDIM) * (int)sizeof(float); // 73728
    cudaFuncSetAttribute(gemm_k, cudaFuncAttributeMaxDynamicSharedMemorySize, smem_bytes);

    softmax_k<<<1, NPART>>>(logp);
    group_k<<<(BATCH + 255) / 256, 256>>>(randind, wout, rout);
    gemm_k<<<NPART, 256, smem_bytes>>>(gaussian, pos, sigma, out);
}

// round 5
// speedup vs baseline: 3.2439x; 1.3765x over previous
#include <cuda_runtime.h>
#include <cuda_bf16.h>
#include <cstddef>

#define NPART 128
#define NDIM  128
#define BATCH 4096
#define TILE_B 16

// ---------------------------------------------------------------------------
// Fully fused kernel: one CTA per particle.
//   phase 1: softmax over logp (redundant per-CTA, cheap)
//   phase 2: scan randind, build own sample list, emit weights/rout
//   phase 3: stage sigma[p]^T to smem, batched matvec over own samples
// ---------------------------------------------------------------------------
__global__ __launch_bounds__(256) void fused_k(
    const float* __restrict__ gaussian,
    const float* __restrict__ logp,
    const float* __restrict__ pos,
    const float* __restrict__ sigma,
    const int*   __restrict__ randind,
    float*       __restrict__ out,
    float*       __restrict__ wout,
    float*       __restrict__ rout)
{
    extern __shared__ float smem[];
    float* sig_t = smem;                 // [128][128] transposed sigma
    float* ysh   = smem + NDIM * NDIM;   // [TILE_B][128]
    __shared__ int   list[BATCH];        // this CTA's sample indices (16KB)
    __shared__ float red[NPART];
    __shared__ int   s_count;

    const int p   = blockIdx.x;
    const int tid = threadIdx.x;

    // ---- phase 1: softmax probability for particle p ----
    if (tid == 0) s_count = 0;
    if (tid < NPART) red[tid] = logp[tid];
    __syncthreads();
    #pragma unroll
    for (int s = 64; s > 0; s >>= 1) {
        if (tid < s) red[tid] = fmaxf(red[tid], red[tid + s]);
        __syncthreads();
    }
    const float m = red[0];
    __syncthreads();
    if (tid < NPART) red[tid] = __expf(logp[tid] - m);
    __syncthreads();
    #pragma unroll
    for (int s = 64; s > 0; s >>= 1) {
        if (tid < s) red[tid] = red[tid] + red[tid + s];
        __syncthreads();
    }
    const float pp = __expf(logp[p] - m) / red[0];

    // ---- phase 2: scan randind, collect own samples, write aux outputs ----
    #pragma unroll
    for (int b = tid; b < BATCH; b += 256) {
        int r = __ldg(&randind[b]);
        if (r == p) {
            int slot = atomicAdd(&s_count, 1);
            list[slot] = b;
            if (wout) wout[b] = pp;
            if (rout) rout[b] = (float)p;
        }
    }

    // ---- phase 3a: stage sigma[p] transposed ----
    {
        const int i  = tid & 127;
        const int jh = (tid >> 7) * 64;
        const float4* srow = (const float4*)(sigma + ((size_t)p * NDIM + i) * NDIM + jh);
        #pragma unroll
        for (int jj = 0; jj < 16; jj++) {
            float4 v = __ldg(&srow[jj]);
            int j = jh + jj * 4;
            sig_t[(j + 0) * NDIM + i] = v.x;
            sig_t[(j + 1) * NDIM + i] = v.y;
            sig_t[(j + 2) * NDIM + i] = v.z;
            sig_t[(j + 3) * NDIM + i] = v.w;
        }
    }
    __syncthreads();               // list + count + sig_t complete
    const int count = s_count;

    // ---- phase 3b: batched matvec over own samples ----
    const int tx = tid & 31;       // 32 i-groups of 4
    const int ty = tid >> 5;       // 8 b-groups of 2
    const int i0 = tx * 4;

    const float4 pv = __ldg((const float4*)(pos + (size_t)p * NDIM + i0));

    const int ntiles = (count + TILE_B - 1) / TILE_B;

    for (int t = 0; t < ntiles; t++) {
        const int base = t * TILE_B;

        if (t > 0) __syncthreads();          // protect previous tile's ysh
        // stage y tile, vectorized: TILE_B rows x 32 float4
        #pragma unroll
        for (int idx = tid; idx < TILE_B * 32; idx += 256) {
            int bl = idx >> 5;               // 0..15
            int j4 = idx & 31;
            int gi = base + bl;
            float4 v = make_float4(0.f, 0.f, 0.f, 0.f);
            if (gi < count)
                v = __ldg((const float4*)(gaussian + (size_t)list[gi] * NDIM) + j4);
            *((float4*)(ysh + bl * NDIM) + j4) = v;
        }
        __syncthreads();

        float a0x = 0.f, a0y = 0.f, a0z = 0.f, a0w = 0.f;
        float a1x = 0.f, a1y = 0.f, a1z = 0.f, a1w = 0.f;
        const float* y0 = ysh + (ty * 2 + 0) * NDIM;
        const float* y1 = ysh + (ty * 2 + 1) * NDIM;

        #pragma unroll 8
        for (int j = 0; j < NDIM; j++) {
            float4 s = *(const float4*)(sig_t + j * NDIM + i0);
            float ya = y0[j];
            float yb = y1[j];
            a0x = fmaf(s.x, ya, a0x); a0y = fmaf(s.y, ya, a0y);
            a0z = fmaf(s.z, ya, a0z); a0w = fmaf(s.w, ya, a0w);
            a1x = fmaf(s.x, yb, a1x); a1y = fmaf(s.y, yb, a1y);
            a1z = fmaf(s.z, yb, a1z); a1w = fmaf(s.w, yb, a1w);
        }

        int gi0 = base + ty * 2 + 0;
        int gi1 = base + ty * 2 + 1;
        if (gi0 < count) {
            int b = list[gi0];
            float4 o; o.x = pv.x + a0x; o.y = pv.y + a0y; o.z = pv.z + a0z; o.w = pv.w + a0w;
            *(float4*)(out + (size_t)b * NDIM + i0) = o;
        }
        if (gi1 < count) {
            int b = list[gi1];
            float4 o; o.x = pv.x + a1x; o.y = pv.y + a1y; o.z = pv.z + a1z; o.w = pv.w + a1w;
            *(float4*)(out + (size_t)b * NDIM + i0) = o;
        }
    }
}

// ---------------------------------------------------------------------------
// Launch
// ---------------------------------------------------------------------------
extern "C" void kernel_launch(void* const* d_in, const int* in_sizes, int n_in,
                              void* d_out, int out_size)
{
    const float* gaussian = nullptr;
    const float* logp     = nullptr;
    const float* pos      = nullptr;
    const float* sigma    = nullptr;
    const int*   randind  = nullptr;

    for (int k = 0; k < n_in; k++) {
        switch (in_sizes[k]) {
            case BATCH * NDIM:        gaussian = (const float*)d_in[k]; break;
            case NPART:               logp     = (const float*)d_in[k]; break;
            case NPART * NDIM:        pos      = (const float*)d_in[k]; break;
            case NPART * NDIM * NDIM: sigma    = (const float*)d_in[k]; break;
            case BATCH:               randind  = (const int*)d_in[k];   break;
            default: break;
        }
    }

    float* out  = (float*)d_out;
    float* wout = nullptr;
    float* rout = nullptr;
    const int OUT_MAIN = BATCH * NDIM;
    if (out_size >= OUT_MAIN + BATCH)     wout = out + OUT_MAIN;
    if (out_size >= OUT_MAIN + 2 * BATCH) rout = out + OUT_MAIN + BATCH;

    const int smem_bytes = (NDIM * NDIM + TILE_B * NDIM) * (int)sizeof(float); // 73728
    cudaFuncSetAttribute(fused_k, cudaFuncAttributeMaxDynamicSharedMemorySize, smem_bytes);

    fused_k<<<NPART, 256, smem_bytes>>>(gaussian, logp, pos, sigma, randind,
                                        out, wout, rout);
}